// round 1
// baseline (speedup 1.0000x reference)
#include <cuda_runtime.h>
#include <math.h>

// ---------------- problem constants ----------------
#define CD     512
#define HF     38
#define WF     38
#define HW     1444          // 38*38
#define NOBJ   64
#define NREL   256
#define NIMG   2
#define NPIX   49            // 7*7
#define FC1K   25088         // 512*49
#define FCH    4096
#define MAPN   1536
#define OUTN   51
#define ROWS_PW 92416        // 64*1444
#define PW_PART_BLOCKS 1024
#define PW_ROWS_PER 91       // ceil(92416/1024)

// ---------------- scratch (device globals; no allocation allowed) ----------------
__device__ float g_dwf   [NOBJ*4608];
__device__ float g_pwf   [NOBJ*CD*CD];            // [n][d][c]
__device__ float g_rf    [NIMG*CD*HW];            // [b][o][p]
__device__ float g_dw    [NOBJ*CD*HW];            // [n][c][p]
__device__ float g_pw    [NOBJ*HW*CD];            // [n][p][d]   (pixel-major!)
__device__ float g_dwinv [CD];
__device__ float g_dwsh  [CD];
__device__ float g_partS [PW_PART_BLOCKS*CD];
__device__ float g_partQ [PW_PART_BLOCKS*CD];
__device__ float g_pwinv [CD];
__device__ float g_pwsh  [CD];
__device__ float g_SO    [NREL*NPIX*1024];        // [r*49+pix][role*512+c]
__device__ float g_flat  [NREL*FC1K];             // [r][o*49+pix]
__device__ float g_h1    [NREL*FCH];
__device__ float g_rel   [NREL*FCH];
__device__ float g_sub   [NOBJ*1024];
__device__ float g_cat   [NREL*1024];
__device__ float g_lo    [NREL*MAPN];
__device__ float g_lr    [NREL*MAPN];
__device__ float g_t     [NREL*MAPN];

// ---------------- generic tiled SGEMM ----------------
// C[M,N] = op( A[M,K] @ B[K,N] + bias ),  128x128x16 tiles, 8x8 microtile, 256 threads.
// TA: A accessed as A[k*lda+m];  TB: B accessed as B[n*ldb+k].
// BNA: A element transformed v*inv[k]+sh[k] on load.
// BIAS: 0 none, 1 per-col(n), 2 per-row(m).  RELU: max(0,.)
// OUTROI: store at (m/49)*25088 + n*49 + (m%49)  (rec -> flat scatter)
// Requires K % 16 == 0 (true for all uses here).
template<bool TA, bool TB, bool BNA, int BIAS, bool RELU, bool OUTROI>
__global__ __launch_bounds__(256)
void gemm_k(const float* __restrict__ A, const float* __restrict__ B,
            const float* __restrict__ bias, float* __restrict__ Cc,
            int M, int N, int K, int lda, int ldb, int ldc,
            long sA, long sB, long sC,
            const float* __restrict__ bninv, const float* __restrict__ bnsh)
{
    __shared__ float As[16][128];
    __shared__ float Bs[16][128];

    A  += (long)blockIdx.z * sA;
    B  += (long)blockIdx.z * sB;
    Cc += (long)blockIdx.z * sC;

    const int m0 = blockIdx.y * 128;
    const int n0 = blockIdx.x * 128;
    const int tid = threadIdx.x;
    const int tx = tid & 15;
    const int ty = tid >> 4;

    float acc[8][8];
#pragma unroll
    for (int i = 0; i < 8; i++)
#pragma unroll
        for (int j = 0; j < 8; j++) acc[i][j] = 0.f;

    for (int k0 = 0; k0 < K; k0 += 16) {
        // load A tile
#pragma unroll
        for (int i = 0; i < 8; i++) {
            int idx = tid + i * 256;
            int m, k;
            if (TA) { k = idx >> 7; m = idx & 127; }
            else    { m = idx >> 4; k = idx & 15; }
            int gm = m0 + m, gk = k0 + k;
            float v = 0.f;
            if (gm < M) {
                v = TA ? A[(long)gk * lda + gm] : A[(long)gm * lda + gk];
                if (BNA) v = v * bninv[gk] + bnsh[gk];
            }
            As[k][m] = v;
        }
        // load B tile
#pragma unroll
        for (int i = 0; i < 8; i++) {
            int idx = tid + i * 256;
            int n, k;
            if (TB) { n = idx >> 4; k = idx & 15; }
            else    { k = idx >> 7; n = idx & 127; }
            int gn = n0 + n, gk = k0 + k;
            float v = 0.f;
            if (gn < N) v = TB ? B[(long)gn * ldb + gk] : B[(long)gk * ldb + gn];
            Bs[k][n] = v;
        }
        __syncthreads();
#pragma unroll
        for (int k = 0; k < 16; k++) {
            float4 a0 = *reinterpret_cast<const float4*>(&As[k][ty * 8]);
            float4 a1 = *reinterpret_cast<const float4*>(&As[k][ty * 8 + 4]);
            float4 b0 = *reinterpret_cast<const float4*>(&Bs[k][tx * 8]);
            float4 b1 = *reinterpret_cast<const float4*>(&Bs[k][tx * 8 + 4]);
            float a[8] = {a0.x,a0.y,a0.z,a0.w,a1.x,a1.y,a1.z,a1.w};
            float b[8] = {b0.x,b0.y,b0.z,b0.w,b1.x,b1.y,b1.z,b1.w};
#pragma unroll
            for (int i = 0; i < 8; i++)
#pragma unroll
                for (int j = 0; j < 8; j++)
                    acc[i][j] += a[i] * b[j];
        }
        __syncthreads();
    }
    // epilogue
#pragma unroll
    for (int i = 0; i < 8; i++) {
        int gm = m0 + ty * 8 + i;
        if (gm >= M) continue;
#pragma unroll
        for (int j = 0; j < 8; j++) {
            int gn = n0 + tx * 8 + j;
            if (gn >= N) continue;
            float v = acc[i][j];
            if (BIAS == 1) v += bias[gn];
            if (BIAS == 2) v += bias[gm];
            if (RELU) v = fmaxf(v, 0.f);
            long off;
            if (OUTROI) { int r = gm / 49; int p = gm - r * 49; off = (long)r * FC1K + (long)gn * 49 + p; }
            else        { off = (long)gm * ldc + gn; }
            Cc[off] = v;
        }
    }
}

// ---------------- depthwise 3x3 conv (SAME), per (n,c) plane ----------------
__global__ void dwconv_k(const float* __restrict__ rf, const float* __restrict__ dwf,
                         const int* __restrict__ im_inds, float* __restrict__ dw)
{
    int n = blockIdx.x, c = blockIdx.y;
    __shared__ float plane[HW];
    __shared__ float f[9];
    int im = im_inds[n];
    const float* src = rf + ((long)im * CD + c) * HW;
    for (int i = threadIdx.x; i < HW; i += 256) plane[i] = src[i];
    if (threadIdx.x < 9) f[threadIdx.x] = dwf[((long)n * CD + c) * 9 + threadIdx.x];
    __syncthreads();
    float* dst = dw + ((long)n * CD + c) * HW;
    for (int p = threadIdx.x; p < HW; p += 256) {
        int y = p / WF, x = p - y * WF;
        float s = 0.f;
#pragma unroll
        for (int dy = 0; dy < 3; dy++) {
            int yy = y + dy - 1;
            if (yy < 0 || yy >= HF) continue;
#pragma unroll
            for (int dx = 0; dx < 3; dx++) {
                int xx = x + dx - 1;
                if (xx < 0 || xx >= WF) continue;
                s += plane[yy * WF + xx] * f[dy * 3 + dx];
            }
        }
        dst[p] = s;
    }
}

// ---------------- dw BN stats (one block per channel c, deterministic) ----------------
__global__ void dwstats_k(const float* __restrict__ dw, const float* __restrict__ scale,
                          const float* __restrict__ bias, float* __restrict__ inv,
                          float* __restrict__ sh)
{
    int c = blockIdx.x;
    double s = 0.0, q = 0.0;
    for (int n = 0; n < NOBJ; n++) {
        const float* row = dw + ((long)n * CD + c) * HW;
        for (int p = threadIdx.x; p < HW; p += 256) {
            float v = row[p];
            s += v; q += (double)v * v;
        }
    }
    __shared__ double rs[256], rq[256];
    rs[threadIdx.x] = s; rq[threadIdx.x] = q;
    __syncthreads();
    for (int o = 128; o > 0; o >>= 1) {
        if (threadIdx.x < o) { rs[threadIdx.x] += rs[threadIdx.x + o]; rq[threadIdx.x] += rq[threadIdx.x + o]; }
        __syncthreads();
    }
    if (threadIdx.x == 0) {
        double cnt = (double)ROWS_PW;
        double m = rs[0] / cnt;
        double var = rq[0] / cnt - m * m;
        float iv = scale[c] * (float)(1.0 / sqrt(var + 1e-5));
        inv[c] = iv;
        sh[c]  = bias[c] - (float)m * iv;
    }
}

// ---------------- pw BN stats: stage 1 partials (deterministic) ----------------
__global__ void pwpart_k(const float* __restrict__ pw, float* __restrict__ pS, float* __restrict__ pQ)
{
    int blk = blockIdx.x;         // 1024 blocks
    int t = threadIdx.x;          // 256 threads: handles d=t and d=t+256
    float s0 = 0, q0 = 0, s1 = 0, q1 = 0;
    int r0 = blk * PW_ROWS_PER;
    int r1 = min(ROWS_PW, r0 + PW_ROWS_PER);
    for (int r = r0; r < r1; r++) {
        const float* row = pw + (long)r * CD;
        float v0 = row[t], v1 = row[t + 256];
        s0 += v0; q0 += v0 * v0;
        s1 += v1; q1 += v1 * v1;
    }
    pS[(long)blk * CD + t] = s0;       pS[(long)blk * CD + t + 256] = s1;
    pQ[(long)blk * CD + t] = q0;       pQ[(long)blk * CD + t + 256] = q1;
}

// ---------------- pw BN stats: stage 2 finalize ----------------
__global__ void pwfin_k(const float* __restrict__ pS, const float* __restrict__ pQ,
                        const float* __restrict__ scale, const float* __restrict__ bias,
                        float* __restrict__ inv, float* __restrict__ sh)
{
    int d = blockIdx.x;
    double s = 0.0, q = 0.0;
    for (int b = threadIdx.x; b < PW_PART_BLOCKS; b += 256) {
        s += pS[(long)b * CD + d];
        q += pQ[(long)b * CD + d];
    }
    __shared__ double rs[256], rq[256];
    rs[threadIdx.x] = s; rq[threadIdx.x] = q;
    __syncthreads();
    for (int o = 128; o > 0; o >>= 1) {
        if (threadIdx.x < o) { rs[threadIdx.x] += rs[threadIdx.x + o]; rq[threadIdx.x] += rq[threadIdx.x + o]; }
        __syncthreads();
    }
    if (threadIdx.x == 0) {
        double cnt = (double)ROWS_PW;
        double m = rs[0] / cnt;
        double var = rq[0] / cnt - m * m;
        float iv = scale[d] * (float)(1.0 / sqrt(var + 1e-5));
        inv[d] = iv;
        sh[d]  = bias[d] - (float)m * iv;
    }
}

// ---------------- ROI-align 7x7 with fused BN+ReLU at the gather ----------------
__global__ void roi_k(const float* __restrict__ pw, const float* __restrict__ boxes,
                      const int* __restrict__ rel_inds, const float* __restrict__ inv,
                      const float* __restrict__ sh, float* __restrict__ SO)
{
    int b = blockIdx.x;           // 512 blocks: (rel, role)
    int r = b >> 1, role = b & 1;
    int obj = rel_inds[r * 2 + role];

    __shared__ int yi0[7], yi1[7], xi0[7], xi1[7];
    __shared__ float wy[7], wx[7];
    if (threadIdx.x < 14) {
        int i = threadIdx.x % 7;
        bool isY = threadIdx.x < 7;
        float lo = boxes[obj * 4 + (isY ? 1 : 0)] * (1.0f / 16.0f);
        float hi = boxes[obj * 4 + (isY ? 3 : 2)] * (1.0f / 16.0f);
        float g = ((float)i + 0.5f) / 7.0f;
        float v = lo + (hi - lo) * g;
        float f0 = floorf(v);
        float w = v - f0;
        int i0 = min(max((int)f0, 0), HF - 1);
        int i1 = min(i0 + 1, HF - 1);
        if (isY) { yi0[i] = i0; yi1[i] = i1; wy[i] = w; }
        else     { xi0[i] = i0; xi1[i] = i1; wx[i] = w; }
    }
    __syncthreads();

    const float* base = pw + (long)obj * HW * CD;
    float* dst = SO + (long)r * NPIX * 1024 + role * CD;

    for (int e = threadIdx.x; e < NPIX * CD; e += 256) {
        int pix = e >> 9;
        int c = e & 511;
        int iy = pix / 7, ix = pix - iy * 7;
        int y0 = yi0[iy], y1 = yi1[iy], x0 = xi0[ix], x1 = xi1[ix];
        float fy = wy[iy], fx = wx[ix];
        float ivv = inv[c], shv = sh[c];
        float v00 = fmaxf(base[(long)(y0 * WF + x0) * CD + c] * ivv + shv, 0.f);
        float v01 = fmaxf(base[(long)(y0 * WF + x1) * CD + c] * ivv + shv, 0.f);
        float v10 = fmaxf(base[(long)(y1 * WF + x0) * CD + c] * ivv + shv, 0.f);
        float v11 = fmaxf(base[(long)(y1 * WF + x1) * CD + c] * ivv + shv, 0.f);
        float out = v00 * (1.f - fy) * (1.f - fx) + v01 * (1.f - fy) * fx
                  + v10 * fy * (1.f - fx)         + v11 * fy * fx;
        dst[(long)pix * 1024 + c] = out;
    }
}

// ---------------- gather/concat subobj rows per relation ----------------
__global__ void cat_k(const float* __restrict__ sub, const int* __restrict__ rel_inds,
                      float* __restrict__ cat)
{
    int idx = blockIdx.x * 256 + threadIdx.x;
    if (idx >= NREL * 1024) return;
    int r = idx >> 10;
    int c = idx & 1023;
    int obj = rel_inds[r * 2 + (c < 512 ? 0 : 1)];
    cat[idx] = sub[(long)obj * 1024 + c];
}

// ---------------- triple = relu(lo+lr) - (lo-lr)^2 ----------------
__global__ void triple_k(const float* __restrict__ lo, const float* __restrict__ lr,
                         float* __restrict__ t)
{
    int idx = blockIdx.x * 256 + threadIdx.x;
    if (idx >= NREL * MAPN) return;
    float a = lo[idx], b = lr[idx];
    float d = a - b;
    t[idx] = fmaxf(a + b, 0.f) - d * d;
}

// ---------------- host side ----------------
static inline dim3 ggrid(int M, int N, int Z) {
    return dim3((unsigned)((N + 127) / 128), (unsigned)((M + 127) / 128), (unsigned)Z);
}

extern "C" void kernel_launch(void* const* d_in, const int* in_sizes, int n_in,
                              void* d_out, int out_size)
{
    (void)in_sizes; (void)n_in; (void)out_size;
    const float* fmaps     = (const float*)d_in[0];
    const float* boxes     = (const float*)d_in[1];
    const float* rof       = (const float*)d_in[2];
    const float* reduce_w  = (const float*)d_in[3];
    const float* reduce_b  = (const float*)d_in[4];
    const float* dw_gen_w  = (const float*)d_in[5];
    const float* dw_gen_b  = (const float*)d_in[6];
    const float* pw_gen_w  = (const float*)d_in[7];
    const float* pw_gen_b  = (const float*)d_in[8];
    const float* dw_bns    = (const float*)d_in[9];
    const float* dw_bnb    = (const float*)d_in[10];
    const float* pw_bns    = (const float*)d_in[11];
    const float* pw_bnb    = (const float*)d_in[12];
    const float* recover_w = (const float*)d_in[13];
    const float* recover_b = (const float*)d_in[14];
    const float* fc1_w     = (const float*)d_in[15];
    const float* fc1_b     = (const float*)d_in[16];
    const float* fc2_w     = (const float*)d_in[17];
    const float* fc2_b     = (const float*)d_in[18];
    const float* post_w    = (const float*)d_in[19];
    const float* post_b    = (const float*)d_in[20];
    const float* map_w     = (const float*)d_in[21];
    const float* map_b     = (const float*)d_in[22];
    const float* rr_w      = (const float*)d_in[23];
    const float* rr_b      = (const float*)d_in[24];
    const float* comp_w    = (const float*)d_in[25];
    const float* comp_b    = (const float*)d_in[26];
    const int*   im_inds   = (const int*)d_in[27];
    const int*   rel_inds  = (const int*)d_in[28];
    float* out = (float*)d_out;

    float *p_dwf, *p_pwf, *p_rf, *p_dw, *p_pw, *p_dwinv, *p_dwsh, *p_pS, *p_pQ,
          *p_pwinv, *p_pwsh, *p_SO, *p_flat, *p_h1, *p_rel, *p_sub, *p_cat,
          *p_lo, *p_lr, *p_t;
    cudaGetSymbolAddress((void**)&p_dwf, g_dwf);
    cudaGetSymbolAddress((void**)&p_pwf, g_pwf);
    cudaGetSymbolAddress((void**)&p_rf, g_rf);
    cudaGetSymbolAddress((void**)&p_dw, g_dw);
    cudaGetSymbolAddress((void**)&p_pw, g_pw);
    cudaGetSymbolAddress((void**)&p_dwinv, g_dwinv);
    cudaGetSymbolAddress((void**)&p_dwsh, g_dwsh);
    cudaGetSymbolAddress((void**)&p_pS, g_partS);
    cudaGetSymbolAddress((void**)&p_pQ, g_partQ);
    cudaGetSymbolAddress((void**)&p_pwinv, g_pwinv);
    cudaGetSymbolAddress((void**)&p_pwsh, g_pwsh);
    cudaGetSymbolAddress((void**)&p_SO, g_SO);
    cudaGetSymbolAddress((void**)&p_flat, g_flat);
    cudaGetSymbolAddress((void**)&p_h1, g_h1);
    cudaGetSymbolAddress((void**)&p_rel, g_rel);
    cudaGetSymbolAddress((void**)&p_sub, g_sub);
    cudaGetSymbolAddress((void**)&p_cat, g_cat);
    cudaGetSymbolAddress((void**)&p_lo, g_lo);
    cudaGetSymbolAddress((void**)&p_lr, g_lr);
    cudaGetSymbolAddress((void**)&p_t, g_t);

    // 1) dw_f = rof @ dw_gen_w + b          (64 x 4608, K=512)
    gemm_k<false,false,false,1,false,false><<<ggrid(NOBJ,4608,1),256>>>(
        rof, dw_gen_w, dw_gen_b, p_dwf, NOBJ,4608,512, 512,4608,4608, 0,0,0, nullptr,nullptr);

    // 2) pw_f = rof @ pw_gen_w + b          (64 x 262144, K=512)  -- 536MB weight stream
    gemm_k<false,false,false,1,false,false><<<ggrid(NOBJ,262144,1),256>>>(
        rof, pw_gen_w, pw_gen_b, p_pwf, NOBJ,262144,512, 512,262144,262144, 0,0,0, nullptr,nullptr);

    // 3) rf[b][o][p] = relu(sum_c fm[b][c][p] * W[c][o] + rb[o])   per-image GEMM
    gemm_k<true,false,false,2,true,false><<<ggrid(CD,HW,NIMG),256>>>(
        reduce_w, fmaps, reduce_b, p_rf, CD,HW,CD, CD,HW,HW,
        0, (long)CD*HW, (long)CD*HW, nullptr,nullptr);

    // 4) depthwise conv per (n,c)
    dwconv_k<<<dim3(NOBJ,CD),256>>>(p_rf, p_dwf, im_inds, p_dw);

    // 5) dw BN params
    dwstats_k<<<CD,256>>>(p_dw, dw_bns, dw_bnb, p_dwinv, p_dwsh);

    // 6) pw[n][p][d] = sum_c bn(dw[n][c][p]) * pwf[n][d][c]    (64 batched GEMMs, 48 GFLOP)
    gemm_k<true,true,true,0,false,false><<<ggrid(HW,CD,NOBJ),256>>>(
        p_dw, p_pwf, nullptr, p_pw, HW,CD,CD, HW,CD,CD,
        (long)CD*HW, (long)CD*CD, (long)HW*CD, p_dwinv, p_dwsh);

    // 7) pw BN stats (deterministic two-stage)
    pwpart_k<<<PW_PART_BLOCKS,256>>>(p_pw, p_pS, p_pQ);
    pwfin_k<<<CD,256>>>(p_pS, p_pQ, pw_bns, pw_bnb, p_pwinv, p_pwsh);

    // 8) ROI align (bn+relu fused at gather), writes SO[r*49+pix][role*512+c]
    roi_k<<<NREL*2,256>>>(p_pw, boxes, rel_inds, p_pwinv, p_pwsh, p_SO);

    // 9) rec = SO @ recover_w + b, scattered into flat[r][o*49+pix]   (12544x512, K=1024)
    gemm_k<false,false,false,1,false,true><<<ggrid(NREL*NPIX,CD,1),256>>>(
        p_SO, recover_w, recover_b, p_flat, NREL*NPIX,CD,1024, 1024,CD,0, 0,0,0, nullptr,nullptr);

    // 10) h1 = relu(flat @ fc1_w + b)       (256x4096, K=25088, 411MB weight)
    gemm_k<false,false,false,1,true,false><<<ggrid(NREL,FCH,1),256>>>(
        p_flat, fc1_w, fc1_b, p_h1, NREL,FCH,FC1K, FC1K,FCH,FCH, 0,0,0, nullptr,nullptr);

    // 11) rel = h1 @ fc2_w + b              (256x4096, K=4096)
    gemm_k<false,false,false,1,false,false><<<ggrid(NREL,FCH,1),256>>>(
        p_h1, fc2_w, fc2_b, p_rel, NREL,FCH,FCH, FCH,FCH,FCH, 0,0,0, nullptr,nullptr);

    // 12) subobj = rof @ post_obj_w + b     (64x1024, K=512)
    gemm_k<false,false,false,1,false,false><<<ggrid(NOBJ,1024,1),256>>>(
        rof, post_w, post_b, p_sub, NOBJ,1024,512, 512,1024,1024, 0,0,0, nullptr,nullptr);

    // 13) cat rows
    cat_k<<<(NREL*1024+255)/256,256>>>(p_sub, rel_inds, p_cat);

    // 14) last_obj = cat @ mapping_w + b    (256x1536, K=1024)
    gemm_k<false,false,false,1,false,false><<<ggrid(NREL,MAPN,1),256>>>(
        p_cat, map_w, map_b, p_lo, NREL,MAPN,1024, 1024,MAPN,MAPN, 0,0,0, nullptr,nullptr);

    // 15) last_rel = rel @ rel_red_w + b    (256x1536, K=4096)
    gemm_k<false,false,false,1,false,false><<<ggrid(NREL,MAPN,1),256>>>(
        p_rel, rr_w, rr_b, p_lr, NREL,MAPN,FCH, FCH,MAPN,MAPN, 0,0,0, nullptr,nullptr);

    // 16) triple
    triple_k<<<(NREL*MAPN+255)/256,256>>>(p_lo, p_lr, p_t);

    // 17) out = triple @ comp_w + b         (256x51, K=1536)
    gemm_k<false,false,false,1,false,false><<<ggrid(NREL,OUTN,1),256>>>(
        p_t, comp_w, comp_b, out, NREL,OUTN,MAPN, MAPN,OUTN,OUTN, 0,0,0, nullptr,nullptr);
}

// round 2
// speedup vs baseline: 1.6371x; 1.6371x over previous
#include <cuda_runtime.h>
#include <math.h>

// ---------------- problem constants ----------------
#define CD     512
#define HF     38
#define WF     38
#define HW     1444          // 38*38
#define NOBJ   64
#define NREL   256
#define NIMG   2
#define NPIX   49            // 7*7
#define FC1K   25088         // 512*49
#define FCH    4096
#define MAPN   1536
#define OUTN   51
#define ROWS_PW 92416        // 64*1444
#define PW_PART_BLOCKS 1024
#define PW_ROWS_PER 91       // ceil(92416/1024)

// ---------------- scratch (device globals; no allocation allowed) ----------------
__device__ float g_dwf   [NOBJ*4608];
__device__ float g_pwf   [NOBJ*CD*CD];            // [n][d][c]
__device__ float g_rf    [NIMG*CD*HW];            // [b][o][p]
__device__ float g_dw    [NOBJ*CD*HW];            // [n][c][p]
__device__ float g_pw    [NOBJ*HW*CD];            // [n][p][d]   (pixel-major!)
__device__ float g_dwinv [CD];
__device__ float g_dwsh  [CD];
__device__ float g_partS [PW_PART_BLOCKS*CD];
__device__ float g_partQ [PW_PART_BLOCKS*CD];
__device__ float g_pwinv [CD];
__device__ float g_pwsh  [CD];
__device__ float g_SO    [NREL*NPIX*1024];        // [r*49+pix][role*512+c]
__device__ float g_flat  [NREL*FC1K];             // [r][o*49+pix]
__device__ float g_h1    [NREL*FCH];
__device__ float g_rel   [NREL*FCH];
__device__ float g_sub   [NOBJ*1024];
__device__ float g_cat   [NREL*1024];
__device__ float g_lo    [NREL*MAPN];
__device__ float g_lr    [NREL*MAPN];
__device__ float g_t     [NREL*MAPN];
__device__ float g_part  [8*256*4096];            // split-K partials (33.5MB), reused serially

// ---------------- main tiled SGEMM: 128x128, double-buffered, 1 sync/tile ----------------
// TA: A[k*lda+m]; TB: B[n*ldb+k]; BNA: a = a*inv[k]+sh[k]
// BIAS: 0 none, 1 per-col, 2 per-row. OUTROI: scatter rec->flat.
// SPLITK: blockIdx.z = K-chunk index (kc wide), output partial [z][m][n] (stride N), no bias.
// otherwise blockIdx.z = batch (strides sA,sB,sC). K (or kc) must be multiple of 16.
template<bool TA, bool TB, bool BNA, int BIAS, bool RELU, bool OUTROI, bool SPLITK>
__global__ __launch_bounds__(256)
void gemm_k(const float* __restrict__ A, const float* __restrict__ B,
            const float* __restrict__ bias, float* __restrict__ Cc,
            int M, int N, int K, int kc, int lda, int ldb, int ldc,
            long sA, long sB, long sC,
            const float* __restrict__ bninv, const float* __restrict__ bnsh)
{
    __shared__ float As[2][16][128];
    __shared__ float Bs[2][16][128];

    int k0, kend;
    if (SPLITK) { k0 = blockIdx.z * kc; kend = k0 + kc; }
    else {
        A += (long)blockIdx.z * sA; B += (long)blockIdx.z * sB; Cc += (long)blockIdx.z * sC;
        k0 = 0; kend = K;
    }

    const int m0 = blockIdx.y * 128;
    const int n0 = blockIdx.x * 128;
    const int tid = threadIdx.x;
    const int tx = tid & 15;
    const int ty = tid >> 4;

    float acc[8][8];
#pragma unroll
    for (int i = 0; i < 8; i++)
#pragma unroll
        for (int j = 0; j < 8; j++) acc[i][j] = 0.f;

    // prologue: tile k0 -> buf 0
#pragma unroll
    for (int i = 0; i < 8; i++) {
        int idx = tid + i * 256; int m, k;
        if (TA) { k = idx >> 7; m = idx & 127; } else { m = idx >> 4; k = idx & 15; }
        int gm = m0 + m, gk = k0 + k;
        float v = 0.f;
        if (gm < M) {
            v = TA ? A[(long)gk * lda + gm] : A[(long)gm * lda + gk];
            if (BNA) v = v * bninv[gk] + bnsh[gk];
        }
        As[0][k][m] = v;
    }
#pragma unroll
    for (int i = 0; i < 8; i++) {
        int idx = tid + i * 256; int n, k;
        if (TB) { n = idx >> 4; k = idx & 15; } else { k = idx >> 7; n = idx & 127; }
        int gn = n0 + n, gk = k0 + k;
        float v = 0.f;
        if (gn < N) v = TB ? B[(long)gn * ldb + gk] : B[(long)gk * ldb + gn];
        Bs[0][k][n] = v;
    }
    __syncthreads();

    int bb = 0;
    for (int kt = k0 + 16; ; kt += 16) {
        bool nxt = kt < kend;
        float ra[8], rb[8];
        if (nxt) {
#pragma unroll
            for (int i = 0; i < 8; i++) {
                int idx = tid + i * 256; int m, k;
                if (TA) { k = idx >> 7; m = idx & 127; } else { m = idx >> 4; k = idx & 15; }
                int gm = m0 + m, gk = kt + k;
                float v = 0.f;
                if (gm < M) {
                    v = TA ? A[(long)gk * lda + gm] : A[(long)gm * lda + gk];
                    if (BNA) v = v * bninv[gk] + bnsh[gk];
                }
                ra[i] = v;
            }
#pragma unroll
            for (int i = 0; i < 8; i++) {
                int idx = tid + i * 256; int n, k;
                if (TB) { n = idx >> 4; k = idx & 15; } else { k = idx >> 7; n = idx & 127; }
                int gn = n0 + n, gk = kt + k;
                float v = 0.f;
                if (gn < N) v = TB ? B[(long)gn * ldb + gk] : B[(long)gk * ldb + gn];
                rb[i] = v;
            }
        }
#pragma unroll
        for (int k = 0; k < 16; k++) {
            float4 a0 = *reinterpret_cast<const float4*>(&As[bb][k][ty * 4]);
            float4 a1 = *reinterpret_cast<const float4*>(&As[bb][k][64 + ty * 4]);
            float4 b0 = *reinterpret_cast<const float4*>(&Bs[bb][k][tx * 4]);
            float4 b1 = *reinterpret_cast<const float4*>(&Bs[bb][k][64 + tx * 4]);
            float a[8] = {a0.x,a0.y,a0.z,a0.w,a1.x,a1.y,a1.z,a1.w};
            float b[8] = {b0.x,b0.y,b0.z,b0.w,b1.x,b1.y,b1.z,b1.w};
#pragma unroll
            for (int i = 0; i < 8; i++)
#pragma unroll
                for (int j = 0; j < 8; j++)
                    acc[i][j] += a[i] * b[j];
        }
        if (!nxt) break;
        int nb = bb ^ 1;
#pragma unroll
        for (int i = 0; i < 8; i++) {
            int idx = tid + i * 256; int m, k;
            if (TA) { k = idx >> 7; m = idx & 127; } else { m = idx >> 4; k = idx & 15; }
            As[nb][k][m] = ra[i];
        }
#pragma unroll
        for (int i = 0; i < 8; i++) {
            int idx = tid + i * 256; int n, k;
            if (TB) { n = idx >> 4; k = idx & 15; } else { k = idx >> 7; n = idx & 127; }
            Bs[nb][k][n] = rb[i];
        }
        __syncthreads();
        bb = nb;
    }

    // epilogue
#pragma unroll
    for (int i = 0; i < 8; i++) {
        int gm = m0 + ((i < 4) ? ty * 4 + i : 64 + ty * 4 + (i - 4));
        if (gm >= M) continue;
#pragma unroll
        for (int j = 0; j < 8; j++) {
            int gn = n0 + ((j < 4) ? tx * 4 + j : 64 + tx * 4 + (j - 4));
            if (gn >= N) continue;
            float v = acc[i][j];
            if (SPLITK) {
                Cc[((long)blockIdx.z * M + gm) * (long)N + gn] = v;
            } else {
                if (BIAS == 1) v += bias[gn];
                if (BIAS == 2) v += bias[gm];
                if (RELU) v = fmaxf(v, 0.f);
                long off;
                if (OUTROI) { int r = gm / 49; int p = gm - r * 49; off = (long)r * FC1K + (long)gn * 49 + p; }
                else        { off = (long)gm * ldc + gn; }
                Cc[off] = v;
            }
        }
    }
}

// ---------------- skinny SGEMM: 64(M) x 128(N), vectorized, double-buffered ----------------
// A row-major [M,K] (lda%4==0), B row-major [K,N]. grid(x=N/128, y=M/64, z=S).
// VECB: N%128==0 and ldb%4==0 -> float4 B loads. DIRECT: write C with bias(+relu);
// otherwise write split-K partial [z][m][n] (stride N). kc must be multiple of 16, M%64==0.
template<bool VECB, bool DIRECT, bool RELU>
__global__ __launch_bounds__(256)
void gemm_sk(const float* __restrict__ A, const float* __restrict__ B,
             const float* __restrict__ bias, float* __restrict__ Cc,
             int M, int N, int kc, int lda, int ldb, int ldc)
{
    __shared__ float As[2][16][64];
    __shared__ float Bs[2][16][128];
    const int m0 = blockIdx.y * 64, n0 = blockIdx.x * 128;
    const int k0 = blockIdx.z * kc;
    const int tid = threadIdx.x, tx = tid & 15, ty = tid >> 4;
    const int am = tid >> 2, akq = (tid & 3) * 4;
    const int bk = tid >> 4, bn = (tid & 15) * 8;

    float acc[4][8];
#pragma unroll
    for (int i = 0; i < 4; i++)
#pragma unroll
        for (int j = 0; j < 8; j++) acc[i][j] = 0.f;

    {   // prologue tile
        float4 v = *reinterpret_cast<const float4*>(&A[(long)(m0 + am) * lda + k0 + akq]);
        As[0][akq + 0][am] = v.x; As[0][akq + 1][am] = v.y;
        As[0][akq + 2][am] = v.z; As[0][akq + 3][am] = v.w;
        if (VECB) {
            float4 b0v = *reinterpret_cast<const float4*>(&B[(long)(k0 + bk) * ldb + n0 + bn]);
            float4 b1v = *reinterpret_cast<const float4*>(&B[(long)(k0 + bk) * ldb + n0 + bn + 4]);
            *reinterpret_cast<float4*>(&Bs[0][bk][bn]) = b0v;
            *reinterpret_cast<float4*>(&Bs[0][bk][bn + 4]) = b1v;
        } else {
#pragma unroll
            for (int j = 0; j < 8; j++) {
                int gn = n0 + bn + j;
                Bs[0][bk][bn + j] = (gn < N) ? B[(long)(k0 + bk) * ldb + gn] : 0.f;
            }
        }
    }
    __syncthreads();

    int bb = 0;
    for (int kt = k0 + 16; ; kt += 16) {
        bool nxt = kt < k0 + kc;
        float4 va, vb0, vb1; float sb[8];
        if (nxt) {
            va = *reinterpret_cast<const float4*>(&A[(long)(m0 + am) * lda + kt + akq]);
            if (VECB) {
                vb0 = *reinterpret_cast<const float4*>(&B[(long)(kt + bk) * ldb + n0 + bn]);
                vb1 = *reinterpret_cast<const float4*>(&B[(long)(kt + bk) * ldb + n0 + bn + 4]);
            } else {
#pragma unroll
                for (int j = 0; j < 8; j++) {
                    int gn = n0 + bn + j;
                    sb[j] = (gn < N) ? B[(long)(kt + bk) * ldb + gn] : 0.f;
                }
            }
        }
#pragma unroll
        for (int k = 0; k < 16; k++) {
            float4 a0 = *reinterpret_cast<const float4*>(&As[bb][k][ty * 4]);
            float4 b0 = *reinterpret_cast<const float4*>(&Bs[bb][k][tx * 4]);
            float4 b1 = *reinterpret_cast<const float4*>(&Bs[bb][k][64 + tx * 4]);
            float a[4] = {a0.x,a0.y,a0.z,a0.w};
            float b[8] = {b0.x,b0.y,b0.z,b0.w,b1.x,b1.y,b1.z,b1.w};
#pragma unroll
            for (int i = 0; i < 4; i++)
#pragma unroll
                for (int j = 0; j < 8; j++)
                    acc[i][j] += a[i] * b[j];
        }
        if (!nxt) break;
        int nb = bb ^ 1;
        As[nb][akq + 0][am] = va.x; As[nb][akq + 1][am] = va.y;
        As[nb][akq + 2][am] = va.z; As[nb][akq + 3][am] = va.w;
        if (VECB) {
            *reinterpret_cast<float4*>(&Bs[nb][bk][bn]) = vb0;
            *reinterpret_cast<float4*>(&Bs[nb][bk][bn + 4]) = vb1;
        } else {
#pragma unroll
            for (int j = 0; j < 8; j++) Bs[nb][bk][bn + j] = sb[j];
        }
        __syncthreads();
        bb = nb;
    }

#pragma unroll
    for (int i = 0; i < 4; i++) {
        int gm = m0 + ty * 4 + i;
#pragma unroll
        for (int j = 0; j < 8; j++) {
            int gn = n0 + ((j < 4) ? tx * 4 + j : 64 + tx * 4 + (j - 4));
            if (gn >= N) continue;
            float v = acc[i][j];
            if (DIRECT) {
                v += bias[gn];
                if (RELU) v = fmaxf(v, 0.f);
                Cc[(long)gm * ldc + gn] = v;
            } else {
                Cc[((long)blockIdx.z * M + gm) * (long)N + gn] = v;
            }
        }
    }
}

// ---------------- split-K reduce: C = sum_s part[s] + bias (per-col), optional relu ----------------
__global__ void reduce_k(const float* __restrict__ part, const float* __restrict__ bias,
                         float* __restrict__ C, int M, int N, int S, int ldc, int relu)
{
    int idx = blockIdx.x * 256 + threadIdx.x;
    if (idx >= M * N) return;
    int m = idx / N, n = idx - m * N;
    float v = 0.f;
    for (int s = 0; s < S; s++) v += part[(long)s * M * N + idx];
    v += bias[n];
    if (relu) v = fmaxf(v, 0.f);
    C[(long)m * ldc + n] = v;
}

// ---------------- depthwise 3x3 conv (SAME), per (n,c) plane ----------------
__global__ void dwconv_k(const float* __restrict__ rf, const float* __restrict__ dwf,
                         const int* __restrict__ im_inds, float* __restrict__ dw)
{
    int n = blockIdx.x, c = blockIdx.y;
    __shared__ float plane[HW];
    __shared__ float f[9];
    int im = im_inds[n];
    const float* src = rf + ((long)im * CD + c) * HW;
    for (int i = threadIdx.x; i < HW; i += 256) plane[i] = src[i];
    if (threadIdx.x < 9) f[threadIdx.x] = dwf[((long)n * CD + c) * 9 + threadIdx.x];
    __syncthreads();
    float* dst = dw + ((long)n * CD + c) * HW;
    for (int p = threadIdx.x; p < HW; p += 256) {
        int y = p / WF, x = p - y * WF;
        float s = 0.f;
#pragma unroll
        for (int dy = 0; dy < 3; dy++) {
            int yy = y + dy - 1;
            if (yy < 0 || yy >= HF) continue;
#pragma unroll
            for (int dx = 0; dx < 3; dx++) {
                int xx = x + dx - 1;
                if (xx < 0 || xx >= WF) continue;
                s += plane[yy * WF + xx] * f[dy * 3 + dx];
            }
        }
        dst[p] = s;
    }
}

// ---------------- dw BN stats (one block per channel, deterministic) ----------------
__global__ void dwstats_k(const float* __restrict__ dw, const float* __restrict__ scale,
                          const float* __restrict__ bias, float* __restrict__ inv,
                          float* __restrict__ sh)
{
    int c = blockIdx.x;
    double s = 0.0, q = 0.0;
    for (int n = 0; n < NOBJ; n++) {
        const float* row = dw + ((long)n * CD + c) * HW;
        for (int p = threadIdx.x; p < HW; p += 256) {
            float v = row[p];
            s += v; q += (double)v * v;
        }
    }
    __shared__ double rs[256], rq[256];
    rs[threadIdx.x] = s; rq[threadIdx.x] = q;
    __syncthreads();
    for (int o = 128; o > 0; o >>= 1) {
        if (threadIdx.x < o) { rs[threadIdx.x] += rs[threadIdx.x + o]; rq[threadIdx.x] += rq[threadIdx.x + o]; }
        __syncthreads();
    }
    if (threadIdx.x == 0) {
        double cnt = (double)ROWS_PW;
        double m = rs[0] / cnt;
        double var = rq[0] / cnt - m * m;
        float iv = scale[c] * (float)(1.0 / sqrt(var + 1e-5));
        inv[c] = iv;
        sh[c]  = bias[c] - (float)m * iv;
    }
}

// ---------------- pw BN stats: stage 1 partials ----------------
__global__ void pwpart_k(const float* __restrict__ pw, float* __restrict__ pS, float* __restrict__ pQ)
{
    int blk = blockIdx.x;
    int t = threadIdx.x;
    float s0 = 0, q0 = 0, s1 = 0, q1 = 0;
    int r0 = blk * PW_ROWS_PER;
    int r1 = min(ROWS_PW, r0 + PW_ROWS_PER);
    for (int r = r0; r < r1; r++) {
        const float* row = pw + (long)r * CD;
        float v0 = row[t], v1 = row[t + 256];
        s0 += v0; q0 += v0 * v0;
        s1 += v1; q1 += v1 * v1;
    }
    pS[(long)blk * CD + t] = s0;       pS[(long)blk * CD + t + 256] = s1;
    pQ[(long)blk * CD + t] = q0;       pQ[(long)blk * CD + t + 256] = q1;
}

// ---------------- pw BN stats: stage 2 finalize ----------------
__global__ void pwfin_k(const float* __restrict__ pS, const float* __restrict__ pQ,
                        const float* __restrict__ scale, const float* __restrict__ bias,
                        float* __restrict__ inv, float* __restrict__ sh)
{
    int d = blockIdx.x;
    double s = 0.0, q = 0.0;
    for (int b = threadIdx.x; b < PW_PART_BLOCKS; b += 256) {
        s += pS[(long)b * CD + d];
        q += pQ[(long)b * CD + d];
    }
    __shared__ double rs[256], rq[256];
    rs[threadIdx.x] = s; rq[threadIdx.x] = q;
    __syncthreads();
    for (int o = 128; o > 0; o >>= 1) {
        if (threadIdx.x < o) { rs[threadIdx.x] += rs[threadIdx.x + o]; rq[threadIdx.x] += rq[threadIdx.x + o]; }
        __syncthreads();
    }
    if (threadIdx.x == 0) {
        double cnt = (double)ROWS_PW;
        double m = rs[0] / cnt;
        double var = rq[0] / cnt - m * m;
        float iv = scale[d] * (float)(1.0 / sqrt(var + 1e-5));
        inv[d] = iv;
        sh[d]  = bias[d] - (float)m * iv;
    }
}

// ---------------- ROI-align 7x7 with fused BN+ReLU at the gather ----------------
__global__ void roi_k(const float* __restrict__ pw, const float* __restrict__ boxes,
                      const int* __restrict__ rel_inds, const float* __restrict__ inv,
                      const float* __restrict__ sh, float* __restrict__ SO)
{
    int b = blockIdx.x;
    int r = b >> 1, role = b & 1;
    int obj = rel_inds[r * 2 + role];

    __shared__ int yi0[7], yi1[7], xi0[7], xi1[7];
    __shared__ float wy[7], wx[7];
    if (threadIdx.x < 14) {
        int i = threadIdx.x % 7;
        bool isY = threadIdx.x < 7;
        float lo = boxes[obj * 4 + (isY ? 1 : 0)] * (1.0f / 16.0f);
        float hi = boxes[obj * 4 + (isY ? 3 : 2)] * (1.0f / 16.0f);
        float g = ((float)i + 0.5f) / 7.0f;
        float v = lo + (hi - lo) * g;
        float f0 = floorf(v);
        float w = v - f0;
        int i0 = min(max((int)f0, 0), HF - 1);
        int i1 = min(i0 + 1, HF - 1);
        if (isY) { yi0[i] = i0; yi1[i] = i1; wy[i] = w; }
        else     { xi0[i] = i0; xi1[i] = i1; wx[i] = w; }
    }
    __syncthreads();

    const float* base = pw + (long)obj * HW * CD;
    float* dst = SO + (long)r * NPIX * 1024 + role * CD;

    for (int e = threadIdx.x; e < NPIX * CD; e += 256) {
        int pix = e >> 9;
        int c = e & 511;
        int iy = pix / 7, ix = pix - iy * 7;
        int y0 = yi0[iy], y1 = yi1[iy], x0 = xi0[ix], x1 = xi1[ix];
        float fy = wy[iy], fx = wx[ix];
        float ivv = inv[c], shv = sh[c];
        float v00 = fmaxf(base[(long)(y0 * WF + x0) * CD + c] * ivv + shv, 0.f);
        float v01 = fmaxf(base[(long)(y0 * WF + x1) * CD + c] * ivv + shv, 0.f);
        float v10 = fmaxf(base[(long)(y1 * WF + x0) * CD + c] * ivv + shv, 0.f);
        float v11 = fmaxf(base[(long)(y1 * WF + x1) * CD + c] * ivv + shv, 0.f);
        float out = v00 * (1.f - fy) * (1.f - fx) + v01 * (1.f - fy) * fx
                  + v10 * fy * (1.f - fx)         + v11 * fy * fx;
        dst[(long)pix * 1024 + c] = out;
    }
}

// ---------------- gather/concat subobj rows per relation ----------------
__global__ void cat_k(const float* __restrict__ sub, const int* __restrict__ rel_inds,
                      float* __restrict__ cat)
{
    int idx = blockIdx.x * 256 + threadIdx.x;
    if (idx >= NREL * 1024) return;
    int r = idx >> 10;
    int c = idx & 1023;
    int obj = rel_inds[r * 2 + (c < 512 ? 0 : 1)];
    cat[idx] = sub[(long)obj * 1024 + c];
}

// ---------------- triple = relu(lo+lr) - (lo-lr)^2 ----------------
__global__ void triple_k(const float* __restrict__ lo, const float* __restrict__ lr,
                         float* __restrict__ t)
{
    int idx = blockIdx.x * 256 + threadIdx.x;
    if (idx >= NREL * MAPN) return;
    float a = lo[idx], b = lr[idx];
    float d = a - b;
    t[idx] = fmaxf(a + b, 0.f) - d * d;
}

// ---------------- host side ----------------
static inline dim3 ggrid(int M, int N, int Z) {
    return dim3((unsigned)((N + 127) / 128), (unsigned)((M + 127) / 128), (unsigned)Z);
}

extern "C" void kernel_launch(void* const* d_in, const int* in_sizes, int n_in,
                              void* d_out, int out_size)
{
    (void)in_sizes; (void)n_in; (void)out_size;
    const float* fmaps     = (const float*)d_in[0];
    const float* boxes     = (const float*)d_in[1];
    const float* rof       = (const float*)d_in[2];
    const float* reduce_w  = (const float*)d_in[3];
    const float* reduce_b  = (const float*)d_in[4];
    const float* dw_gen_w  = (const float*)d_in[5];
    const float* dw_gen_b  = (const float*)d_in[6];
    const float* pw_gen_w  = (const float*)d_in[7];
    const float* pw_gen_b  = (const float*)d_in[8];
    const float* dw_bns    = (const float*)d_in[9];
    const float* dw_bnb    = (const float*)d_in[10];
    const float* pw_bns    = (const float*)d_in[11];
    const float* pw_bnb    = (const float*)d_in[12];
    const float* recover_w = (const float*)d_in[13];
    const float* recover_b = (const float*)d_in[14];
    const float* fc1_w     = (const float*)d_in[15];
    const float* fc1_b     = (const float*)d_in[16];
    const float* fc2_w     = (const float*)d_in[17];
    const float* fc2_b     = (const float*)d_in[18];
    const float* post_w    = (const float*)d_in[19];
    const float* post_b    = (const float*)d_in[20];
    const float* map_w     = (const float*)d_in[21];
    const float* map_b     = (const float*)d_in[22];
    const float* rr_w      = (const float*)d_in[23];
    const float* rr_b      = (const float*)d_in[24];
    const float* comp_w    = (const float*)d_in[25];
    const float* comp_b    = (const float*)d_in[26];
    const int*   im_inds   = (const int*)d_in[27];
    const int*   rel_inds  = (const int*)d_in[28];
    float* out = (float*)d_out;

    float *p_dwf, *p_pwf, *p_rf, *p_dw, *p_pw, *p_dwinv, *p_dwsh, *p_pS, *p_pQ,
          *p_pwinv, *p_pwsh, *p_SO, *p_flat, *p_h1, *p_rel, *p_sub, *p_cat,
          *p_lo, *p_lr, *p_t, *p_part;
    cudaGetSymbolAddress((void**)&p_dwf, g_dwf);
    cudaGetSymbolAddress((void**)&p_pwf, g_pwf);
    cudaGetSymbolAddress((void**)&p_rf, g_rf);
    cudaGetSymbolAddress((void**)&p_dw, g_dw);
    cudaGetSymbolAddress((void**)&p_pw, g_pw);
    cudaGetSymbolAddress((void**)&p_dwinv, g_dwinv);
    cudaGetSymbolAddress((void**)&p_dwsh, g_dwsh);
    cudaGetSymbolAddress((void**)&p_pS, g_partS);
    cudaGetSymbolAddress((void**)&p_pQ, g_partQ);
    cudaGetSymbolAddress((void**)&p_pwinv, g_pwinv);
    cudaGetSymbolAddress((void**)&p_pwsh, g_pwsh);
    cudaGetSymbolAddress((void**)&p_SO, g_SO);
    cudaGetSymbolAddress((void**)&p_flat, g_flat);
    cudaGetSymbolAddress((void**)&p_h1, g_h1);
    cudaGetSymbolAddress((void**)&p_rel, g_rel);
    cudaGetSymbolAddress((void**)&p_sub, g_sub);
    cudaGetSymbolAddress((void**)&p_cat, g_cat);
    cudaGetSymbolAddress((void**)&p_lo, g_lo);
    cudaGetSymbolAddress((void**)&p_lr, g_lr);
    cudaGetSymbolAddress((void**)&p_t, g_t);
    cudaGetSymbolAddress((void**)&p_part, g_part);

    // 1) dw_f = rof @ dw_gen_w + b  (64x4608, K=512): skinny split-K S=4
    gemm_sk<true,false,false><<<dim3(36,1,4),256>>>(
        rof, dw_gen_w, nullptr, p_part, 64,4608,128, 512,4608,0);
    reduce_k<<<(64*4608+255)/256,256>>>(p_part, dw_gen_b, p_dwf, 64,4608,4,4608,0);

    // 2) pw_f = rof @ pw_gen_w + b  (64x262144, K=512): skinny direct
    gemm_sk<true,true,false><<<dim3(2048,1,1),256>>>(
        rof, pw_gen_w, pw_gen_b, p_pwf, 64,262144,512, 512,262144,262144);

    // 3) rf[b][o][p] = relu(sum_c fm[b][c][p] * W[c][o] + rb[o])
    gemm_k<true,false,false,2,true,false,false><<<ggrid(CD,HW,NIMG),256>>>(
        reduce_w, fmaps, reduce_b, p_rf, CD,HW,CD,0, CD,HW,HW,
        0, (long)CD*HW, (long)CD*HW, nullptr,nullptr);

    // 4) depthwise conv per (n,c)
    dwconv_k<<<dim3(NOBJ,CD),256>>>(p_rf, p_dwf, im_inds, p_dw);

    // 5) dw BN params
    dwstats_k<<<CD,256>>>(p_dw, dw_bns, dw_bnb, p_dwinv, p_dwsh);

    // 6) pw[n][p][d] = sum_c bn(dw[n][c][p]) * pwf[n][d][c]  (64 batched)
    gemm_k<true,true,true,0,false,false,false><<<ggrid(HW,CD,NOBJ),256>>>(
        p_dw, p_pwf, nullptr, p_pw, HW,CD,CD,0, HW,CD,CD,
        (long)CD*HW, (long)CD*CD, (long)HW*CD, p_dwinv, p_dwsh);

    // 7) pw BN stats
    pwpart_k<<<PW_PART_BLOCKS,256>>>(p_pw, p_pS, p_pQ);
    pwfin_k<<<CD,256>>>(p_pS, p_pQ, pw_bns, pw_bnb, p_pwinv, p_pwsh);

    // 8) ROI align (bn+relu fused)
    roi_k<<<NREL*2,256>>>(p_pw, boxes, rel_inds, p_pwinv, p_pwsh, p_SO);

    // 9) rec = SO @ recover_w + b, scattered into flat  (12544x512, K=1024)
    gemm_k<false,false,false,1,false,true,false><<<ggrid(NREL*NPIX,CD,1),256>>>(
        p_SO, recover_w, recover_b, p_flat, NREL*NPIX,CD,1024,0, 1024,CD,0, 0,0,0, nullptr,nullptr);

    // 10) h1 = relu(flat @ fc1_w + b)  (256x4096, K=25088): split-K S=8
    gemm_k<false,false,false,0,false,false,true><<<dim3(32,2,8),256>>>(
        p_flat, fc1_w, nullptr, p_part, NREL,FCH,FC1K,3136, FC1K,FCH,0, 0,0,0, nullptr,nullptr);
    reduce_k<<<(NREL*FCH+255)/256,256>>>(p_part, fc1_b, p_h1, NREL,FCH,8,FCH,1);

    // 11) rel = h1 @ fc2_w + b  (256x4096, K=4096): split-K S=4
    gemm_k<false,false,false,0,false,false,true><<<dim3(32,2,4),256>>>(
        p_h1, fc2_w, nullptr, p_part, NREL,FCH,FCH,1024, FCH,FCH,0, 0,0,0, nullptr,nullptr);
    reduce_k<<<(NREL*FCH+255)/256,256>>>(p_part, fc2_b, p_rel, NREL,FCH,4,FCH,0);

    // 12) subobj = rof @ post_obj_w + b  (64x1024, K=512): skinny split-K S=8
    gemm_sk<true,false,false><<<dim3(8,1,8),256>>>(
        rof, post_w, nullptr, p_part, 64,1024,64, 512,1024,0);
    reduce_k<<<(64*1024+255)/256,256>>>(p_part, post_b, p_sub, 64,1024,8,1024,0);

    // 13) cat rows
    cat_k<<<(NREL*1024+255)/256,256>>>(p_sub, rel_inds, p_cat);

    // 14) last_obj = cat @ mapping_w + b  (256x1536, K=1024): split-K S=4
    gemm_k<false,false,false,0,false,false,true><<<dim3(12,2,4),256>>>(
        p_cat, map_w, nullptr, p_part, NREL,MAPN,1024,256, 1024,MAPN,0, 0,0,0, nullptr,nullptr);
    reduce_k<<<(NREL*MAPN+255)/256,256>>>(p_part, map_b, p_lo, NREL,MAPN,4,MAPN,0);

    // 15) last_rel = rel @ rel_red_w + b  (256x1536, K=4096): split-K S=8
    gemm_k<false,false,false,0,false,false,true><<<dim3(12,2,8),256>>>(
        p_rel, rr_w, nullptr, p_part, NREL,MAPN,FCH,512, FCH,MAPN,0, 0,0,0, nullptr,nullptr);
    reduce_k<<<(NREL*MAPN+255)/256,256>>>(p_part, rr_b, p_lr, NREL,MAPN,8,MAPN,0);

    // 16) triple
    triple_k<<<(NREL*MAPN+255)/256,256>>>(p_lo, p_lr, p_t);

    // 17) out = triple @ comp_w + b  (256x51, K=1536): split-K S=8
    gemm_k<false,false,false,0,false,false,true><<<dim3(1,2,8),256>>>(
        p_t, comp_w, nullptr, p_part, NREL,OUTN,MAPN,192, MAPN,OUTN,0, 0,0,0, nullptr,nullptr);
    reduce_k<<<(NREL*OUTN+255)/256,256>>>(p_part, comp_b, out, NREL,OUTN,8,OUTN,0);
}

// round 3
// speedup vs baseline: 2.6102x; 1.5944x over previous
#include <cuda_runtime.h>
#include <cuda_bf16.h>
#include <math.h>

// ---------------- problem constants ----------------
#define CD     512
#define HF     38
#define WF     38
#define HW     1444          // 38*38
#define NOBJ   64
#define NREL   256
#define NIMG   2
#define NPIX   49            // 7*7
#define FC1K   25088         // 512*49
#define FCH    4096
#define MAPN   1536
#define OUTN   51
#define ROWS_PW 92416        // 64*1444
#define PW_PART_BLOCKS 1024
#define PW_ROWS_PER 91       // ceil(92416/1024)

// ---------------- scratch (device globals; no allocation allowed) ----------------
__device__ float g_dwf   [NOBJ*4608];
__device__ float g_pwf   [NOBJ*CD*CD];            // [n][d][c]
__device__ float g_rf    [NIMG*CD*HW];            // [b][o][p]
__device__ float g_dw    [NOBJ*CD*HW];            // [n][c][p]
__device__ float g_pw    [NOBJ*HW*CD];            // [n][p][d]   (pixel-major!)
__device__ float g_dwinv [CD];
__device__ float g_dwsh  [CD];
__device__ float g_partS [PW_PART_BLOCKS*CD];
__device__ float g_partQ [PW_PART_BLOCKS*CD];
__device__ float g_pwinv [CD];
__device__ float g_pwsh  [CD];
__device__ float g_SO    [NREL*NPIX*1024];        // [r*49+pix][role*512+c]
__device__ float g_flat  [NREL*FC1K];             // [r][o*49+pix]
__device__ float g_h1    [NREL*FCH];
__device__ float g_rel   [NREL*FCH];
__device__ float g_sub   [NOBJ*1024];
__device__ float g_cat   [NREL*1024];
__device__ float g_lo    [NREL*MAPN];
__device__ float g_lr    [NREL*MAPN];
__device__ float g_t     [NREL*MAPN];
__device__ float g_part  [8*256*4096];            // split-K partials, reused serially

// ---------------- helpers ----------------
__device__ __forceinline__ unsigned packbf(__nv_bfloat16 a, __nv_bfloat16 b) {
    __nv_bfloat162 t = __halves2bfloat162(a, b);
    return *reinterpret_cast<unsigned*>(&t);
}

__device__ __forceinline__ void mma_bf16(float* c, const unsigned* a, const unsigned* b) {
    asm volatile(
        "mma.sync.aligned.m16n8k16.row.col.f32.bf16.bf16.f32 "
        "{%0,%1,%2,%3}, {%4,%5,%6,%7}, {%8,%9}, {%0,%1,%2,%3};\n"
        : "+f"(c[0]), "+f"(c[1]), "+f"(c[2]), "+f"(c[3])
        : "r"(a[0]), "r"(a[1]), "r"(a[2]), "r"(a[3]), "r"(b[0]), "r"(b[1]));
}

// =====================================================================
// Tensor-core GEMM with bf16x3 split (fp32-equivalent precision ~1.5e-5)
// C[M,N] = A @ B, 128x128 tiles, K-stages of 16, double-buffered.
// TA:      A accessed A[k*lda+m], else A[m*lda+k]
// BKMAJOR: B accessed B[k*ldb+n], else B[n*ldb+k]
// BNA:     a = a*inv[k]+sh[k] on load
// BIAS:    0 none, 1 per-col, 2 per-row.  RELU: relu.  OUTROI: rec->flat scatter.
// SPLITK:  z = K-chunk (kc wide), partial out [z][M][N]; else z = batch (sA,sB,sC)
// kc (or K) must be a multiple of 16. N<=... guarded; M guarded.
// =====================================================================
template<bool TA, bool BKMAJOR, bool BNA, int BIAS, bool RELU, bool OUTROI, bool SPLITK>
__global__ __launch_bounds__(256)
void tgemm(const float* __restrict__ A, const float* __restrict__ B,
           const float* __restrict__ bias, float* __restrict__ Cc,
           int M, int N, int K, int kc, int lda, int ldb, int ldc,
           long sA, long sB, long sC,
           const float* __restrict__ bninv, const float* __restrict__ bnsh)
{
    // row stride = 9 words (18 bf16) for conflict mitigation
    __shared__ unsigned Ah[2][1152], Al[2][1152], Bh[2][1152], Bl[2][1152];

    int k0, kend;
    if (SPLITK) { k0 = blockIdx.z * kc; kend = k0 + kc; }
    else {
        A += (long)blockIdx.z * sA; B += (long)blockIdx.z * sB; Cc += (long)blockIdx.z * sC;
        k0 = 0; kend = K;
    }
    const int m0 = blockIdx.y * 128;
    const int n0 = blockIdx.x * 128;
    const int tid = threadIdx.x;
    const int lane = tid & 31, g = lane >> 2, t4 = lane & 3;
    const int wid = tid >> 5, wm = wid >> 2, wn = wid & 3;

    float acc[4][4][4];
#pragma unroll
    for (int a = 0; a < 4; a++)
#pragma unroll
        for (int b = 0; b < 4; b++)
#pragma unroll
            for (int c = 0; c < 4; c++) acc[a][b][c] = 0.f;

    // ---- loaders (8 floats per thread per matrix per stage) ----
    auto ldA = [&](int kt, float* fa) {
#pragma unroll
        for (int i = 0; i < 2; i++) {
            int idx = tid * 2 + i;
            if (!TA) {
                int m = idx >> 2, kq = (idx & 3) * 4;
                int gm = m0 + m, gk = kt + kq;
                float4 v = make_float4(0.f, 0.f, 0.f, 0.f);
                if (gm < M) v = *reinterpret_cast<const float4*>(&A[(long)gm * lda + gk]);
                if (BNA) {
                    v.x = v.x * bninv[gk] + bnsh[gk];
                    v.y = v.y * bninv[gk+1] + bnsh[gk+1];
                    v.z = v.z * bninv[gk+2] + bnsh[gk+2];
                    v.w = v.w * bninv[gk+3] + bnsh[gk+3];
                }
                fa[i*4+0]=v.x; fa[i*4+1]=v.y; fa[i*4+2]=v.z; fa[i*4+3]=v.w;
            } else {
                int k = idx >> 5, mq = (idx & 31) * 4;
                int gk = kt + k;
                float iv = 1.f, sv = 0.f;
                if (BNA) { iv = bninv[gk]; sv = bnsh[gk]; }
#pragma unroll
                for (int j = 0; j < 4; j++) {
                    int gm = m0 + mq + j;
                    float v = (gm < M) ? A[(long)gk * lda + gm] : 0.f;
                    if (BNA) v = v * iv + sv;
                    fa[i*4+j] = v;
                }
            }
        }
    };
    auto ldB = [&](int kt, float* fb) {
#pragma unroll
        for (int i = 0; i < 2; i++) {
            int idx = tid * 2 + i;
            if (BKMAJOR) {
                int k = idx >> 5, nq = (idx & 31) * 4;
                int gk = kt + k;
#pragma unroll
                for (int j = 0; j < 4; j++) {
                    int gn = n0 + nq + j;
                    fb[i*4+j] = (gn < N) ? B[(long)gk * ldb + gn] : 0.f;
                }
            } else {
                int n = idx >> 2, kq = (idx & 3) * 4;
                int gn = n0 + n, gk = kt + kq;
                float4 v = make_float4(0.f, 0.f, 0.f, 0.f);
                if (gn < N) v = *reinterpret_cast<const float4*>(&B[(long)gn * ldb + gk]);
                fb[i*4+0]=v.x; fb[i*4+1]=v.y; fb[i*4+2]=v.z; fb[i*4+3]=v.w;
            }
        }
    };
    auto stA = [&](int s, const float* fa) {
#pragma unroll
        for (int i = 0; i < 2; i++) {
            int idx = tid * 2 + i;
            __nv_bfloat16 h[4], l[4];
#pragma unroll
            for (int j = 0; j < 4; j++) {
                h[j] = __float2bfloat16(fa[i*4+j]);
                l[j] = __float2bfloat16(fa[i*4+j] - __bfloat162float(h[j]));
            }
            if (!TA) {
                int m = idx >> 2, kq = (idx & 3) * 4;
                Ah[s][m*9 + kq/2]     = packbf(h[0], h[1]);
                Ah[s][m*9 + kq/2 + 1] = packbf(h[2], h[3]);
                Al[s][m*9 + kq/2]     = packbf(l[0], l[1]);
                Al[s][m*9 + kq/2 + 1] = packbf(l[2], l[3]);
            } else {
                int k = idx >> 5, mq = (idx & 31) * 4;
                __nv_bfloat16* ph = reinterpret_cast<__nv_bfloat16*>(Ah[s]);
                __nv_bfloat16* pl = reinterpret_cast<__nv_bfloat16*>(Al[s]);
#pragma unroll
                for (int j = 0; j < 4; j++) { ph[(mq+j)*18 + k] = h[j]; pl[(mq+j)*18 + k] = l[j]; }
            }
        }
    };
    auto stB = [&](int s, const float* fb) {
#pragma unroll
        for (int i = 0; i < 2; i++) {
            int idx = tid * 2 + i;
            __nv_bfloat16 h[4], l[4];
#pragma unroll
            for (int j = 0; j < 4; j++) {
                h[j] = __float2bfloat16(fb[i*4+j]);
                l[j] = __float2bfloat16(fb[i*4+j] - __bfloat162float(h[j]));
            }
            if (BKMAJOR) {
                int k = idx >> 5, nq = (idx & 31) * 4;
                __nv_bfloat16* ph = reinterpret_cast<__nv_bfloat16*>(Bh[s]);
                __nv_bfloat16* pl = reinterpret_cast<__nv_bfloat16*>(Bl[s]);
#pragma unroll
                for (int j = 0; j < 4; j++) { ph[(nq+j)*18 + k] = h[j]; pl[(nq+j)*18 + k] = l[j]; }
            } else {
                int n = idx >> 2, kq = (idx & 3) * 4;
                Bh[s][n*9 + kq/2]     = packbf(h[0], h[1]);
                Bh[s][n*9 + kq/2 + 1] = packbf(h[2], h[3]);
                Bl[s][n*9 + kq/2]     = packbf(l[0], l[1]);
                Bl[s][n*9 + kq/2 + 1] = packbf(l[2], l[3]);
            }
        }
    };

    float fa[8], fb[8];
    ldA(k0, fa); ldB(k0, fb);
    stA(0, fa); stB(0, fb);
    __syncthreads();

    int bb = 0;
    for (int kt = k0 + 16; ; kt += 16) {
        bool nxt = kt < kend;
        if (nxt) { ldA(kt, fa); ldB(kt, fb); }

        // compute on stage bb
        unsigned bh[4][2], bl[4][2];
#pragma unroll
        for (int nt = 0; nt < 4; nt++) {
            int cb = (wn * 32 + nt * 8 + g) * 9;
            bh[nt][0] = Bh[bb][cb + t4]; bh[nt][1] = Bh[bb][cb + t4 + 4];
            bl[nt][0] = Bl[bb][cb + t4]; bl[nt][1] = Bl[bb][cb + t4 + 4];
        }
#pragma unroll
        for (int mt = 0; mt < 4; mt++) {
            int ra = (wm * 64 + mt * 16 + g) * 9;
            int rb = ra + 8 * 9;
            unsigned ah[4] = { Ah[bb][ra + t4], Ah[bb][rb + t4], Ah[bb][ra + t4 + 4], Ah[bb][rb + t4 + 4] };
            unsigned al[4] = { Al[bb][ra + t4], Al[bb][rb + t4], Al[bb][ra + t4 + 4], Al[bb][rb + t4 + 4] };
#pragma unroll
            for (int nt = 0; nt < 4; nt++) {
                mma_bf16(acc[mt][nt], ah, bh[nt]);
                mma_bf16(acc[mt][nt], ah, bl[nt]);
                mma_bf16(acc[mt][nt], al, bh[nt]);
            }
        }
        if (!nxt) break;
        int nb = bb ^ 1;
        stA(nb, fa); stB(nb, fb);
        __syncthreads();
        bb = nb;
    }

    // ---- epilogue ----
#pragma unroll
    for (int mt = 0; mt < 4; mt++) {
#pragma unroll
        for (int nt = 0; nt < 4; nt++) {
#pragma unroll
            for (int e = 0; e < 4; e++) {
                int gm = m0 + wm * 64 + mt * 16 + g + ((e >= 2) ? 8 : 0);
                int gn = n0 + wn * 32 + nt * 8 + 2 * t4 + (e & 1);
                if (gm >= M || gn >= N) continue;
                float v = acc[mt][nt][e];
                if (SPLITK) {
                    Cc[((long)blockIdx.z * M + gm) * (long)N + gn] = v;
                } else {
                    if (BIAS == 1) v += bias[gn];
                    if (BIAS == 2) v += bias[gm];
                    if (RELU) v = fmaxf(v, 0.f);
                    long off;
                    if (OUTROI) { int r = gm / 49; int p = gm - r * 49; off = (long)r * FC1K + (long)gn * 49 + p; }
                    else        { off = (long)gm * ldc + gn; }
                    Cc[off] = v;
                }
            }
        }
    }
}

// ---------------- fp32 tiled SGEMM (kept for comp, N=51) ----------------
template<bool TA, bool TB, bool BNA, int BIAS, bool RELU, bool OUTROI, bool SPLITK>
__global__ __launch_bounds__(256)
void gemm_k(const float* __restrict__ A, const float* __restrict__ B,
            const float* __restrict__ bias, float* __restrict__ Cc,
            int M, int N, int K, int kc, int lda, int ldb, int ldc,
            long sA, long sB, long sC,
            const float* __restrict__ bninv, const float* __restrict__ bnsh)
{
    __shared__ float As[2][16][128];
    __shared__ float Bs[2][16][128];

    int k0, kend;
    if (SPLITK) { k0 = blockIdx.z * kc; kend = k0 + kc; }
    else {
        A += (long)blockIdx.z * sA; B += (long)blockIdx.z * sB; Cc += (long)blockIdx.z * sC;
        k0 = 0; kend = K;
    }
    const int m0 = blockIdx.y * 128;
    const int n0 = blockIdx.x * 128;
    const int tid = threadIdx.x;
    const int tx = tid & 15;
    const int ty = tid >> 4;

    float acc[8][8];
#pragma unroll
    for (int i = 0; i < 8; i++)
#pragma unroll
        for (int j = 0; j < 8; j++) acc[i][j] = 0.f;

#pragma unroll
    for (int i = 0; i < 8; i++) {
        int idx = tid + i * 256; int m, k;
        if (TA) { k = idx >> 7; m = idx & 127; } else { m = idx >> 4; k = idx & 15; }
        int gm = m0 + m, gk = k0 + k;
        float v = 0.f;
        if (gm < M) {
            v = TA ? A[(long)gk * lda + gm] : A[(long)gm * lda + gk];
            if (BNA) v = v * bninv[gk] + bnsh[gk];
        }
        As[0][k][m] = v;
    }
#pragma unroll
    for (int i = 0; i < 8; i++) {
        int idx = tid + i * 256; int n, k;
        if (TB) { n = idx >> 4; k = idx & 15; } else { k = idx >> 7; n = idx & 127; }
        int gn = n0 + n, gk = k0 + k;
        float v = 0.f;
        if (gn < N) v = TB ? B[(long)gn * ldb + gk] : B[(long)gk * ldb + gn];
        Bs[0][k][n] = v;
    }
    __syncthreads();

    int bb = 0;
    for (int kt = k0 + 16; ; kt += 16) {
        bool nxt = kt < kend;
        float ra[8], rb[8];
        if (nxt) {
#pragma unroll
            for (int i = 0; i < 8; i++) {
                int idx = tid + i * 256; int m, k;
                if (TA) { k = idx >> 7; m = idx & 127; } else { m = idx >> 4; k = idx & 15; }
                int gm = m0 + m, gk = kt + k;
                float v = 0.f;
                if (gm < M) {
                    v = TA ? A[(long)gk * lda + gm] : A[(long)gm * lda + gk];
                    if (BNA) v = v * bninv[gk] + bnsh[gk];
                }
                ra[i] = v;
            }
#pragma unroll
            for (int i = 0; i < 8; i++) {
                int idx = tid + i * 256; int n, k;
                if (TB) { n = idx >> 4; k = idx & 15; } else { k = idx >> 7; n = idx & 127; }
                int gn = n0 + n, gk = kt + k;
                float v = 0.f;
                if (gn < N) v = TB ? B[(long)gn * ldb + gk] : B[(long)gk * ldb + gn];
                rb[i] = v;
            }
        }
#pragma unroll
        for (int k = 0; k < 16; k++) {
            float4 a0 = *reinterpret_cast<const float4*>(&As[bb][k][ty * 4]);
            float4 a1 = *reinterpret_cast<const float4*>(&As[bb][k][64 + ty * 4]);
            float4 b0 = *reinterpret_cast<const float4*>(&Bs[bb][k][tx * 4]);
            float4 b1 = *reinterpret_cast<const float4*>(&Bs[bb][k][64 + tx * 4]);
            float a[8] = {a0.x,a0.y,a0.z,a0.w,a1.x,a1.y,a1.z,a1.w};
            float b[8] = {b0.x,b0.y,b0.z,b0.w,b1.x,b1.y,b1.z,b1.w};
#pragma unroll
            for (int i = 0; i < 8; i++)
#pragma unroll
                for (int j = 0; j < 8; j++)
                    acc[i][j] += a[i] * b[j];
        }
        if (!nxt) break;
        int nb = bb ^ 1;
#pragma unroll
        for (int i = 0; i < 8; i++) {
            int idx = tid + i * 256; int m, k;
            if (TA) { k = idx >> 7; m = idx & 127; } else { m = idx >> 4; k = idx & 15; }
            As[nb][k][m] = ra[i];
        }
#pragma unroll
        for (int i = 0; i < 8; i++) {
            int idx = tid + i * 256; int n, k;
            if (TB) { n = idx >> 4; k = idx & 15; } else { k = idx >> 7; n = idx & 127; }
            Bs[nb][k][n] = rb[i];
        }
        __syncthreads();
        bb = nb;
    }

#pragma unroll
    for (int i = 0; i < 8; i++) {
        int gm = m0 + ((i < 4) ? ty * 4 + i : 64 + ty * 4 + (i - 4));
        if (gm >= M) continue;
#pragma unroll
        for (int j = 0; j < 8; j++) {
            int gn = n0 + ((j < 4) ? tx * 4 + j : 64 + tx * 4 + (j - 4));
            if (gn >= N) continue;
            float v = acc[i][j];
            if (SPLITK) {
                Cc[((long)blockIdx.z * M + gm) * (long)N + gn] = v;
            } else {
                if (BIAS == 1) v += bias[gn];
                if (BIAS == 2) v += bias[gm];
                if (RELU) v = fmaxf(v, 0.f);
                long off;
                if (OUTROI) { int r = gm / 49; int p = gm - r * 49; off = (long)r * FC1K + (long)gn * 49 + p; }
                else        { off = (long)gm * ldc + gn; }
                Cc[off] = v;
            }
        }
    }
}

// ---------------- skinny SGEMM: 64(M) x 128(N) ----------------
template<bool VECB, bool DIRECT, bool RELU>
__global__ __launch_bounds__(256)
void gemm_sk(const float* __restrict__ A, const float* __restrict__ B,
             const float* __restrict__ bias, float* __restrict__ Cc,
             int M, int N, int kc, int lda, int ldb, int ldc)
{
    __shared__ float As[2][16][64];
    __shared__ float Bs[2][16][128];
    const int m0 = blockIdx.y * 64, n0 = blockIdx.x * 128;
    const int k0 = blockIdx.z * kc;
    const int tid = threadIdx.x, tx = tid & 15, ty = tid >> 4;
    const int am = tid >> 2, akq = (tid & 3) * 4;
    const int bk = tid >> 4, bn = (tid & 15) * 8;

    float acc[4][8];
#pragma unroll
    for (int i = 0; i < 4; i++)
#pragma unroll
        for (int j = 0; j < 8; j++) acc[i][j] = 0.f;

    {
        float4 v = *reinterpret_cast<const float4*>(&A[(long)(m0 + am) * lda + k0 + akq]);
        As[0][akq + 0][am] = v.x; As[0][akq + 1][am] = v.y;
        As[0][akq + 2][am] = v.z; As[0][akq + 3][am] = v.w;
        if (VECB) {
            float4 b0v = *reinterpret_cast<const float4*>(&B[(long)(k0 + bk) * ldb + n0 + bn]);
            float4 b1v = *reinterpret_cast<const float4*>(&B[(long)(k0 + bk) * ldb + n0 + bn + 4]);
            *reinterpret_cast<float4*>(&Bs[0][bk][bn]) = b0v;
            *reinterpret_cast<float4*>(&Bs[0][bk][bn + 4]) = b1v;
        } else {
#pragma unroll
            for (int j = 0; j < 8; j++) {
                int gn = n0 + bn + j;
                Bs[0][bk][bn + j] = (gn < N) ? B[(long)(k0 + bk) * ldb + gn] : 0.f;
            }
        }
    }
    __syncthreads();

    int bb = 0;
    for (int kt = k0 + 16; ; kt += 16) {
        bool nxt = kt < k0 + kc;
        float4 va, vb0, vb1; float sb[8];
        if (nxt) {
            va = *reinterpret_cast<const float4*>(&A[(long)(m0 + am) * lda + kt + akq]);
            if (VECB) {
                vb0 = *reinterpret_cast<const float4*>(&B[(long)(kt + bk) * ldb + n0 + bn]);
                vb1 = *reinterpret_cast<const float4*>(&B[(long)(kt + bk) * ldb + n0 + bn + 4]);
            } else {
#pragma unroll
                for (int j = 0; j < 8; j++) {
                    int gn = n0 + bn + j;
                    sb[j] = (gn < N) ? B[(long)(kt + bk) * ldb + gn] : 0.f;
                }
            }
        }
#pragma unroll
        for (int k = 0; k < 16; k++) {
            float4 a0 = *reinterpret_cast<const float4*>(&As[bb][k][ty * 4]);
            float4 b0 = *reinterpret_cast<const float4*>(&Bs[bb][k][tx * 4]);
            float4 b1 = *reinterpret_cast<const float4*>(&Bs[bb][k][64 + tx * 4]);
            float a[4] = {a0.x,a0.y,a0.z,a0.w};
            float b[8] = {b0.x,b0.y,b0.z,b0.w,b1.x,b1.y,b1.z,b1.w};
#pragma unroll
            for (int i = 0; i < 4; i++)
#pragma unroll
                for (int j = 0; j < 8; j++)
                    acc[i][j] += a[i] * b[j];
        }
        if (!nxt) break;
        int nb = bb ^ 1;
        As[nb][akq + 0][am] = va.x; As[nb][akq + 1][am] = va.y;
        As[nb][akq + 2][am] = va.z; As[nb][akq + 3][am] = va.w;
        if (VECB) {
            *reinterpret_cast<float4*>(&Bs[nb][bk][bn]) = vb0;
            *reinterpret_cast<float4*>(&Bs[nb][bk][bn + 4]) = vb1;
        } else {
#pragma unroll
            for (int j = 0; j < 8; j++) Bs[nb][bk][bn + j] = sb[j];
        }
        __syncthreads();
        bb = nb;
    }

#pragma unroll
    for (int i = 0; i < 4; i++) {
        int gm = m0 + ty * 4 + i;
#pragma unroll
        for (int j = 0; j < 8; j++) {
            int gn = n0 + ((j < 4) ? tx * 4 + j : 64 + tx * 4 + (j - 4));
            if (gn >= N) continue;
            float v = acc[i][j];
            if (DIRECT) {
                v += bias[gn];
                if (RELU) v = fmaxf(v, 0.f);
                Cc[(long)gm * ldc + gn] = v;
            } else {
                Cc[((long)blockIdx.z * M + gm) * (long)N + gn] = v;
            }
        }
    }
}

// ---------------- split-K reduce ----------------
__global__ void reduce_k(const float* __restrict__ part, const float* __restrict__ bias,
                         float* __restrict__ C, int M, int N, int S, int ldc, int relu)
{
    int idx = blockIdx.x * 256 + threadIdx.x;
    if (idx >= M * N) return;
    int m = idx / N, n = idx - m * N;
    float v = 0.f;
    for (int s = 0; s < S; s++) v += part[(long)s * M * N + idx];
    v += bias[n];
    if (relu) v = fmaxf(v, 0.f);
    C[(long)m * ldc + n] = v;
}

// ---------------- depthwise 3x3 conv ----------------
__global__ void dwconv_k(const float* __restrict__ rf, const float* __restrict__ dwf,
                         const int* __restrict__ im_inds, float* __restrict__ dw)
{
    int n = blockIdx.x, c = blockIdx.y;
    __shared__ float plane[HW];
    __shared__ float f[9];
    int im = im_inds[n];
    const float* src = rf + ((long)im * CD + c) * HW;
    for (int i = threadIdx.x; i < HW; i += 256) plane[i] = src[i];
    if (threadIdx.x < 9) f[threadIdx.x] = dwf[((long)n * CD + c) * 9 + threadIdx.x];
    __syncthreads();
    float* dst = dw + ((long)n * CD + c) * HW;
    for (int p = threadIdx.x; p < HW; p += 256) {
        int y = p / WF, x = p - y * WF;
        float s = 0.f;
#pragma unroll
        for (int dy = 0; dy < 3; dy++) {
            int yy = y + dy - 1;
            if (yy < 0 || yy >= HF) continue;
#pragma unroll
            for (int dx = 0; dx < 3; dx++) {
                int xx = x + dx - 1;
                if (xx < 0 || xx >= WF) continue;
                s += plane[yy * WF + xx] * f[dy * 3 + dx];
            }
        }
        dst[p] = s;
    }
}

// ---------------- dw BN stats ----------------
__global__ void dwstats_k(const float* __restrict__ dw, const float* __restrict__ scale,
                          const float* __restrict__ bias, float* __restrict__ inv,
                          float* __restrict__ sh)
{
    int c = blockIdx.x;
    double s = 0.0, q = 0.0;
    for (int n = 0; n < NOBJ; n++) {
        const float* row = dw + ((long)n * CD + c) * HW;
        for (int p = threadIdx.x; p < HW; p += 256) {
            float v = row[p];
            s += v; q += (double)v * v;
        }
    }
    __shared__ double rs[256], rq[256];
    rs[threadIdx.x] = s; rq[threadIdx.x] = q;
    __syncthreads();
    for (int o = 128; o > 0; o >>= 1) {
        if (threadIdx.x < o) { rs[threadIdx.x] += rs[threadIdx.x + o]; rq[threadIdx.x] += rq[threadIdx.x + o]; }
        __syncthreads();
    }
    if (threadIdx.x == 0) {
        double cnt = (double)ROWS_PW;
        double m = rs[0] / cnt;
        double var = rq[0] / cnt - m * m;
        float iv = scale[c] * (float)(1.0 / sqrt(var + 1e-5));
        inv[c] = iv;
        sh[c]  = bias[c] - (float)m * iv;
    }
}

// ---------------- pw BN stats ----------------
__global__ void pwpart_k(const float* __restrict__ pw, float* __restrict__ pS, float* __restrict__ pQ)
{
    int blk = blockIdx.x;
    int t = threadIdx.x;
    float s0 = 0, q0 = 0, s1 = 0, q1 = 0;
    int r0 = blk * PW_ROWS_PER;
    int r1 = min(ROWS_PW, r0 + PW_ROWS_PER);
    for (int r = r0; r < r1; r++) {
        const float* row = pw + (long)r * CD;
        float v0 = row[t], v1 = row[t + 256];
        s0 += v0; q0 += v0 * v0;
        s1 += v1; q1 += v1 * v1;
    }
    pS[(long)blk * CD + t] = s0;       pS[(long)blk * CD + t + 256] = s1;
    pQ[(long)blk * CD + t] = q0;       pQ[(long)blk * CD + t + 256] = q1;
}

__global__ void pwfin_k(const float* __restrict__ pS, const float* __restrict__ pQ,
                        const float* __restrict__ scale, const float* __restrict__ bias,
                        float* __restrict__ inv, float* __restrict__ sh)
{
    int d = blockIdx.x;
    double s = 0.0, q = 0.0;
    for (int b = threadIdx.x; b < PW_PART_BLOCKS; b += 256) {
        s += pS[(long)b * CD + d];
        q += pQ[(long)b * CD + d];
    }
    __shared__ double rs[256], rq[256];
    rs[threadIdx.x] = s; rq[threadIdx.x] = q;
    __syncthreads();
    for (int o = 128; o > 0; o >>= 1) {
        if (threadIdx.x < o) { rs[threadIdx.x] += rs[threadIdx.x + o]; rq[threadIdx.x] += rq[threadIdx.x + o]; }
        __syncthreads();
    }
    if (threadIdx.x == 0) {
        double cnt = (double)ROWS_PW;
        double m = rs[0] / cnt;
        double var = rq[0] / cnt - m * m;
        float iv = scale[d] * (float)(1.0 / sqrt(var + 1e-5));
        inv[d] = iv;
        sh[d]  = bias[d] - (float)m * iv;
    }
}

// ---------------- ROI-align 7x7 with fused BN+ReLU ----------------
__global__ void roi_k(const float* __restrict__ pw, const float* __restrict__ boxes,
                      const int* __restrict__ rel_inds, const float* __restrict__ inv,
                      const float* __restrict__ sh, float* __restrict__ SO)
{
    int b = blockIdx.x;
    int r = b >> 1, role = b & 1;
    int obj = rel_inds[r * 2 + role];

    __shared__ int yi0[7], yi1[7], xi0[7], xi1[7];
    __shared__ float wy[7], wx[7];
    if (threadIdx.x < 14) {
        int i = threadIdx.x % 7;
        bool isY = threadIdx.x < 7;
        float lo = boxes[obj * 4 + (isY ? 1 : 0)] * (1.0f / 16.0f);
        float hi = boxes[obj * 4 + (isY ? 3 : 2)] * (1.0f / 16.0f);
        float g = ((float)i + 0.5f) / 7.0f;
        float v = lo + (hi - lo) * g;
        float f0 = floorf(v);
        float w = v - f0;
        int i0 = min(max((int)f0, 0), HF - 1);
        int i1 = min(i0 + 1, HF - 1);
        if (isY) { yi0[i] = i0; yi1[i] = i1; wy[i] = w; }
        else     { xi0[i] = i0; xi1[i] = i1; wx[i] = w; }
    }
    __syncthreads();

    const float* base = pw + (long)obj * HW * CD;
    float* dst = SO + (long)r * NPIX * 1024 + role * CD;

    for (int e = threadIdx.x; e < NPIX * CD; e += 256) {
        int pix = e >> 9;
        int c = e & 511;
        int iy = pix / 7, ix = pix - iy * 7;
        int y0 = yi0[iy], y1 = yi1[iy], x0 = xi0[ix], x1 = xi1[ix];
        float fy = wy[iy], fx = wx[ix];
        float ivv = inv[c], shv = sh[c];
        float v00 = fmaxf(base[(long)(y0 * WF + x0) * CD + c] * ivv + shv, 0.f);
        float v01 = fmaxf(base[(long)(y0 * WF + x1) * CD + c] * ivv + shv, 0.f);
        float v10 = fmaxf(base[(long)(y1 * WF + x0) * CD + c] * ivv + shv, 0.f);
        float v11 = fmaxf(base[(long)(y1 * WF + x1) * CD + c] * ivv + shv, 0.f);
        float out = v00 * (1.f - fy) * (1.f - fx) + v01 * (1.f - fy) * fx
                  + v10 * fy * (1.f - fx)         + v11 * fy * fx;
        dst[(long)pix * 1024 + c] = out;
    }
}

// ---------------- concat subobj rows ----------------
__global__ void cat_k(const float* __restrict__ sub, const int* __restrict__ rel_inds,
                      float* __restrict__ cat)
{
    int idx = blockIdx.x * 256 + threadIdx.x;
    if (idx >= NREL * 1024) return;
    int r = idx >> 10;
    int c = idx & 1023;
    int obj = rel_inds[r * 2 + (c < 512 ? 0 : 1)];
    cat[idx] = sub[(long)obj * 1024 + c];
}

// ---------------- triple ----------------
__global__ void triple_k(const float* __restrict__ lo, const float* __restrict__ lr,
                         float* __restrict__ t)
{
    int idx = blockIdx.x * 256 + threadIdx.x;
    if (idx >= NREL * MAPN) return;
    float a = lo[idx], b = lr[idx];
    float d = a - b;
    t[idx] = fmaxf(a + b, 0.f) - d * d;
}

// ---------------- host side ----------------
extern "C" void kernel_launch(void* const* d_in, const int* in_sizes, int n_in,
                              void* d_out, int out_size)
{
    (void)in_sizes; (void)n_in; (void)out_size;
    const float* fmaps     = (const float*)d_in[0];
    const float* boxes     = (const float*)d_in[1];
    const float* rof       = (const float*)d_in[2];
    const float* reduce_w  = (const float*)d_in[3];
    const float* reduce_b  = (const float*)d_in[4];
    const float* dw_gen_w  = (const float*)d_in[5];
    const float* dw_gen_b  = (const float*)d_in[6];
    const float* pw_gen_w  = (const float*)d_in[7];
    const float* pw_gen_b  = (const float*)d_in[8];
    const float* dw_bns    = (const float*)d_in[9];
    const float* dw_bnb    = (const float*)d_in[10];
    const float* pw_bns    = (const float*)d_in[11];
    const float* pw_bnb    = (const float*)d_in[12];
    const float* recover_w = (const float*)d_in[13];
    const float* recover_b = (const float*)d_in[14];
    const float* fc1_w     = (const float*)d_in[15];
    const float* fc1_b     = (const float*)d_in[16];
    const float* fc2_w     = (const float*)d_in[17];
    const float* fc2_b     = (const float*)d_in[18];
    const float* post_w    = (const float*)d_in[19];
    const float* post_b    = (const float*)d_in[20];
    const float* map_w     = (const float*)d_in[21];
    const float* map_b     = (const float*)d_in[22];
    const float* rr_w      = (const float*)d_in[23];
    const float* rr_b      = (const float*)d_in[24];
    const float* comp_w    = (const float*)d_in[25];
    const float* comp_b    = (const float*)d_in[26];
    const int*   im_inds   = (const int*)d_in[27];
    const int*   rel_inds  = (const int*)d_in[28];
    float* out = (float*)d_out;

    float *p_dwf, *p_pwf, *p_rf, *p_dw, *p_pw, *p_dwinv, *p_dwsh, *p_pS, *p_pQ,
          *p_pwinv, *p_pwsh, *p_SO, *p_flat, *p_h1, *p_rel, *p_sub, *p_cat,
          *p_lo, *p_lr, *p_t, *p_part;
    cudaGetSymbolAddress((void**)&p_dwf, g_dwf);
    cudaGetSymbolAddress((void**)&p_pwf, g_pwf);
    cudaGetSymbolAddress((void**)&p_rf, g_rf);
    cudaGetSymbolAddress((void**)&p_dw, g_dw);
    cudaGetSymbolAddress((void**)&p_pw, g_pw);
    cudaGetSymbolAddress((void**)&p_dwinv, g_dwinv);
    cudaGetSymbolAddress((void**)&p_dwsh, g_dwsh);
    cudaGetSymbolAddress((void**)&p_pS, g_partS);
    cudaGetSymbolAddress((void**)&p_pQ, g_partQ);
    cudaGetSymbolAddress((void**)&p_pwinv, g_pwinv);
    cudaGetSymbolAddress((void**)&p_pwsh, g_pwsh);
    cudaGetSymbolAddress((void**)&p_SO, g_SO);
    cudaGetSymbolAddress((void**)&p_flat, g_flat);
    cudaGetSymbolAddress((void**)&p_h1, g_h1);
    cudaGetSymbolAddress((void**)&p_rel, g_rel);
    cudaGetSymbolAddress((void**)&p_sub, g_sub);
    cudaGetSymbolAddress((void**)&p_cat, g_cat);
    cudaGetSymbolAddress((void**)&p_lo, g_lo);
    cudaGetSymbolAddress((void**)&p_lr, g_lr);
    cudaGetSymbolAddress((void**)&p_t, g_t);
    cudaGetSymbolAddress((void**)&p_part, g_part);

    // 1) dw_f = rof @ dw_gen_w + b  (64x4608, K=512): skinny fp32 split-K S=4
    gemm_sk<true,false,false><<<dim3(36,1,4),256>>>(
        rof, dw_gen_w, nullptr, p_part, 64,4608,128, 512,4608,0);
    reduce_k<<<(64*4608+255)/256,256>>>(p_part, dw_gen_b, p_dwf, 64,4608,4,4608,0);

    // 2) pw_f = rof @ pw_gen_w + b  (64x262144, K=512): tensor direct
    tgemm<false,true,false,1,false,false,false><<<dim3(2048,1,1),256>>>(
        rof, pw_gen_w, pw_gen_b, p_pwf, 64,262144,512,512, 512,262144,262144,
        0,0,0, nullptr,nullptr);

    // 3) rf[b][o][p] = relu(W^T @ fm + b): tensor, per-image batch
    tgemm<true,true,false,2,true,false,false><<<dim3(12,4,2),256>>>(
        reduce_w, fmaps, reduce_b, p_rf, CD,HW,CD,CD, CD,HW,HW,
        0, (long)CD*HW, (long)CD*HW, nullptr,nullptr);

    // 4) depthwise conv per (n,c)
    dwconv_k<<<dim3(NOBJ,CD),256>>>(p_rf, p_dwf, im_inds, p_dw);

    // 5) dw BN params
    dwstats_k<<<CD,256>>>(p_dw, dw_bns, dw_bnb, p_dwinv, p_dwsh);

    // 6) pw[n][p][d] = sum_c bn(dw[n][c][p]) * pwf[n][d][c]: tensor, batch=64
    tgemm<true,false,true,0,false,false,false><<<dim3(4,12,64),256>>>(
        p_dw, p_pwf, nullptr, p_pw, HW,CD,CD,CD, HW,CD,CD,
        (long)CD*HW, (long)CD*CD, (long)HW*CD, p_dwinv, p_dwsh);

    // 7) pw BN stats
    pwpart_k<<<PW_PART_BLOCKS,256>>>(p_pw, p_pS, p_pQ);
    pwfin_k<<<CD,256>>>(p_pS, p_pQ, pw_bns, pw_bnb, p_pwinv, p_pwsh);

    // 8) ROI align (bn+relu fused)
    roi_k<<<NREL*2,256>>>(p_pw, boxes, rel_inds, p_pwinv, p_pwsh, p_SO);

    // 9) rec = SO @ recover_w + b, ROI-scatter  (12544x512, K=1024): tensor
    tgemm<false,true,false,1,false,true,false><<<dim3(4,98,1),256>>>(
        p_SO, recover_w, recover_b, p_flat, NREL*NPIX,CD,1024,1024, 1024,CD,0,
        0,0,0, nullptr,nullptr);

    // 10) h1 = relu(flat @ fc1_w + b)  (256x4096, K=25088): tensor split-K S=4
    tgemm<false,true,false,0,false,false,true><<<dim3(32,2,4),256>>>(
        p_flat, fc1_w, nullptr, p_part, NREL,FCH,FC1K,6272, FC1K,FCH,0,
        0,0,0, nullptr,nullptr);
    reduce_k<<<(NREL*FCH+255)/256,256>>>(p_part, fc1_b, p_h1, NREL,FCH,4,FCH,1);

    // 11) rel = h1 @ fc2_w + b  (256x4096, K=4096): tensor split-K S=4
    tgemm<false,true,false,0,false,false,true><<<dim3(32,2,4),256>>>(
        p_h1, fc2_w, nullptr, p_part, NREL,FCH,FCH,1024, FCH,FCH,0,
        0,0,0, nullptr,nullptr);
    reduce_k<<<(NREL*FCH+255)/256,256>>>(p_part, fc2_b, p_rel, NREL,FCH,4,FCH,0);

    // 12) subobj = rof @ post_obj_w + b  (64x1024, K=512): skinny fp32 split-K S=8
    gemm_sk<true,false,false><<<dim3(8,1,8),256>>>(
        rof, post_w, nullptr, p_part, 64,1024,64, 512,1024,0);
    reduce_k<<<(64*1024+255)/256,256>>>(p_part, post_b, p_sub, 64,1024,8,1024,0);

    // 13) cat rows
    cat_k<<<(NREL*1024+255)/256,256>>>(p_sub, rel_inds, p_cat);

    // 14) last_obj = cat @ mapping_w + b  (256x1536, K=1024): tensor split-K S=4
    tgemm<false,true,false,0,false,false,true><<<dim3(12,2,4),256>>>(
        p_cat, map_w, nullptr, p_part, NREL,MAPN,1024,256, 1024,MAPN,0,
        0,0,0, nullptr,nullptr);
    reduce_k<<<(NREL*MAPN+255)/256,256>>>(p_part, map_b, p_lo, NREL,MAPN,4,MAPN,0);

    // 15) last_rel = rel @ rel_red_w + b  (256x1536, K=4096): tensor split-K S=8
    tgemm<false,true,false,0,false,false,true><<<dim3(12,2,8),256>>>(
        p_rel, rr_w, nullptr, p_part, NREL,MAPN,FCH,512, FCH,MAPN,0,
        0,0,0, nullptr,nullptr);
    reduce_k<<<(NREL*MAPN+255)/256,256>>>(p_part, rr_b, p_lr, NREL,MAPN,8,MAPN,0);

    // 16) triple
    triple_k<<<(NREL*MAPN+255)/256,256>>>(p_lo, p_lr, p_t);

    // 17) out = triple @ comp_w + b  (256x51, K=1536): fp32 split-K S=8
    gemm_k<false,false,false,0,false,false,true><<<dim3(1,2,8),256>>>(
        p_t, comp_w, nullptr, p_part, NREL,OUTN,MAPN,192, MAPN,OUTN,OUTN,
        0,0,0, nullptr,nullptr);
    reduce_k<<<(NREL*OUTN+255)/256,256>>>(p_part, comp_b, out, NREL,OUTN,8,OUTN,0);
}